// round 2
// baseline (speedup 1.0000x reference)
#include <cuda_runtime.h>

// FeatureTransformer_5909875000395
// Inputs (metadata order):
//   d_in[0]: ft_ics  int32  [16384, 32]   (pad = -1)
//   d_in[1]: weight  fp32   [41024, 257]
//   d_in[2]: bias    fp32   [256]
// Output: fts [16384,256] followed by psqt [16384,1]  (fp32, 16384*257 elems)
//
// Reference bias semantics: bias_full = [0, bias[0..255]], added across all
// 257 columns. So fts col 0 has no bias, fts col c gets bias[c-1], and the
// psqt column (257th) gets bias[255].

#define BATCH      16384
#define MAX_ACTIVE 32
#define N_OUT      256
#define ROW_W      257   // N_OUT + 1 (psqt column)

__global__ __launch_bounds__(288, 4)
void ft_gather_sum_kernel(const int*   __restrict__ ft_ics,
                          const float* __restrict__ weight,
                          const float* __restrict__ bias,
                          float*       __restrict__ out)
{
    const int row = blockIdx.x;
    const int col = threadIdx.x;

    __shared__ int sidx[MAX_ACTIVE];
    if (threadIdx.x < MAX_ACTIVE)
        sidx[threadIdx.x] = ft_ics[row * MAX_ACTIVE + threadIdx.x];
    __syncthreads();

    if (col >= ROW_W) return;   // threads 257..287 idle after the smem fill

    // Shifted bias: column 0 gets 0, column c gets bias[c-1] (incl. psqt col).
    float acc = (col == 0) ? 0.0f : bias[col - 1];

    // Fully unrolled: 32 independent predicated LDGs -> deep MLP,
    // L2-resident gather (weight table is 42 MB, fits in 126 MB L2).
    #pragma unroll
    for (int i = 0; i < MAX_ACTIVE; ++i) {
        const int idx = sidx[i];
        if (idx >= 0) {
            acc += __ldg(weight + (size_t)idx * ROW_W + col);
        }
    }

    if (col < N_OUT) {
        out[(size_t)row * N_OUT + col] = acc;
    } else { // col == 256 -> psqt
        out[(size_t)BATCH * N_OUT + row] = acc;
    }
}

extern "C" void kernel_launch(void* const* d_in, const int* in_sizes, int n_in,
                              void* d_out, int out_size)
{
    const int*   ft_ics = (const int*)  d_in[0];
    const float* weight = (const float*)d_in[1];
    const float* bias   = (const float*)d_in[2];
    float*       out    = (float*)      d_out;

    ft_gather_sum_kernel<<<BATCH, 288>>>(ft_ics, weight, bias, out);
}